// round 3
// baseline (speedup 1.0000x reference)
#include <cuda_runtime.h>
#include <cuda_bf16.h>

// SegEncodeLoss fused single kernel, round 3.
// Key fixes vs r2: __launch_bounds__(256,4) so ptxas keeps all 8 int4 loads
// in flight (r2 had regs=32 -> serialized batch, MLP_eff << 8), and preds is
// prefetched at entry (independent of the mask) removing the dependent
// second memory round-trip.

constexpr int Hc = 1024, Wc = 1024, Cc = 19;
constexpr int NBLK = 32 * 32 * 32;            // 32768 tiles
constexpr int TPC  = 8;                       // tiles per CTA (1 warp each)
constexpr int NCTA = NBLK / TPC;              // 4096

__device__ float    g_part[NCTA];
__device__ unsigned g_count = 0;              // self-resets via atomicInc limit

__global__ void __launch_bounds__(256, 4) seg_fused_kernel(
    const float* __restrict__ preds,
    const int*   __restrict__ targets,
    float*       __restrict__ out)
{
    const int tid  = threadIdx.x;
    const int warp = tid >> 5;                // tile within CTA
    const int lane = tid & 31;

    const int n  = blockIdx.x * TPC + warp;   // global tile id
    const int b  = n >> 10;
    const int bh = (n >> 5) & 31;
    const int bw = n & 31;

    // Prefetch this tile's logit (lanes 0..18) BEFORE the targets loads:
    // independent of the mask, so its latency overlaps the 8 tile loads.
    float x = 0.0f;
    if (lane < Cc) x = __ldg(&preds[n * Cc + lane]);

    // Tile base as int4 index. Row stride = 256 int4.
    const int rb = lane >> 3;                 // 0..3
    const int c4 = lane & 7;                  // 0..7
    const int4* base = reinterpret_cast<const int4*>(targets)
                     + (size_t)b * (Hc * Wc / 4)
                     + (size_t)(bh * 32 + rb) * (Wc / 4)
                     + bw * 8 + c4;

    // 8 independent 16B loads (rows rb, rb+4, ..., rb+28). With 64 regs
    // available these all issue back-to-back: MLP_p1 = 8.
    int4 v0 = __ldg(base + 0 * 1024);
    int4 v1 = __ldg(base + 1 * 1024);
    int4 v2 = __ldg(base + 2 * 1024);
    int4 v3 = __ldg(base + 3 * 1024);
    int4 v4 = __ldg(base + 4 * 1024);
    int4 v5 = __ldg(base + 5 * 1024);
    int4 v6 = __ldg(base + 6 * 1024);
    int4 v7 = __ldg(base + 7 * 1024);

    unsigned m = (1u << v0.x) | (1u << v0.y) | (1u << v0.z) | (1u << v0.w);
    m |= (1u << v1.x) | (1u << v1.y) | (1u << v1.z) | (1u << v1.w);
    m |= (1u << v2.x) | (1u << v2.y) | (1u << v2.z) | (1u << v2.w);
    m |= (1u << v3.x) | (1u << v3.y) | (1u << v3.z) | (1u << v3.w);
    m |= (1u << v4.x) | (1u << v4.y) | (1u << v4.z) | (1u << v4.w);
    m |= (1u << v5.x) | (1u << v5.y) | (1u << v5.z) | (1u << v5.w);
    m |= (1u << v6.x) | (1u << v6.y) | (1u << v6.z) | (1u << v6.w);
    m |= (1u << v7.x) | (1u << v7.y) | (1u << v7.z) | (1u << v7.w);
    m = __reduce_or_sync(0xffffffffu, m);     // full 32x32 tile mask

    // BCE-with-logits: max(x,0) - x*t + log1p(exp(-|x|)). x already loaded.
    float loss = 0.0f;
    if (lane < Cc) {
        const float t = ((m >> lane) & 1u) ? 1.0f : 0.0f;
        loss = fmaxf(x, 0.0f) - x * t + log1pf(__expf(-fabsf(x)));
    }
    #pragma unroll
    for (int o = 16; o > 0; o >>= 1)
        loss += __shfl_down_sync(0xffffffffu, loss, o);

    __shared__ float s_part[TPC];
    __shared__ bool  s_last;
    if (lane == 0) s_part[warp] = loss;
    __syncthreads();

    if (tid == 0) {
        float cs = 0.0f;
        #pragma unroll
        for (int i = 0; i < TPC; i++) cs += s_part[i];
        g_part[blockIdx.x] = cs;
        __threadfence();
        unsigned old = atomicInc(&g_count, NCTA - 1u);   // wraps to 0: replay-safe
        s_last = (old == NCTA - 1u);
    }
    __syncthreads();

    if (s_last) {
        double s = 0.0;
        for (int i = tid; i < NCTA; i += 256)
            s += (double)__ldcg(&g_part[i]);
        #pragma unroll
        for (int o = 16; o > 0; o >>= 1)
            s += __shfl_down_sync(0xffffffffu, s, o);
        __shared__ double sh[8];
        if (lane == 0) sh[warp] = s;
        __syncthreads();
        if (tid < 8) {
            double t2 = sh[tid];
            #pragma unroll
            for (int o = 4; o > 0; o >>= 1)
                t2 += __shfl_down_sync(0x000000ffu, t2, o);
            if (tid == 0)
                out[0] = (float)(t2 / ((double)NBLK * (double)Cc));
        }
    }
}

extern "C" void kernel_launch(void* const* d_in, const int* in_sizes, int n_in,
                              void* d_out, int out_size) {
    const float* preds   = (const float*)d_in[0];
    const int*   targets = (const int*)d_in[1];
    float*       out     = (float*)d_out;

    seg_fused_kernel<<<NCTA, 256>>>(preds, targets, out);
}

// round 4
// speedup vs baseline: 1.1362x; 1.1362x over previous
#include <cuda_runtime.h>
#include <cuda_bf16.h>

// SegEncodeLoss fused kernel, round 4.
// r3 lesson: per-warp MLP wasn't the limit; the serial per-tile tail
// (REDUX/BCE/shfl) and the CTA-wide wait on warp0's global atomic starved
// the memory pipe (~52% DRAM). Fixes:
//  - 4 tiles per warp, software-pipelined: tile i's loads issue, then tile
//    i-1's REDUX+BCE fills the issue->consume window. Shfl reduce once/4 tiles.
//  - warps 1..7 exit after writing their partial; only warp0 touches the
//    global counter, so no warp waits on an ATOMG round-trip.

constexpr int Hc = 1024, Wc = 1024, Cc = 19;
constexpr int NBLK = 32 * 32 * 32;          // 32768 tiles
constexpr int TPW  = 4;                     // tiles per warp (pipelined)
constexpr int WPC  = 8;                     // warps per CTA
constexpr int NCTA = NBLK / (TPW * WPC);    // 1024

__device__ float    g_part[NCTA];
__device__ unsigned g_count = 0;            // wraps to 0 via atomicInc limit

__device__ __forceinline__ float bce_logit(float x, float t) {
    return fmaxf(x, 0.0f) - x * t + log1pf(__expf(-fabsf(x)));
}

__global__ void __launch_bounds__(256, 4) seg_fused_kernel(
    const float* __restrict__ preds,
    const int*   __restrict__ targets,
    float*       __restrict__ out)
{
    const int tid  = threadIdx.x;
    const int warp = tid >> 5;
    const int lane = tid & 31;

    const int gw = blockIdx.x * WPC + warp;  // global warp id
    const int n0 = gw * TPW;                 // first of 4 consecutive tiles
    const int b  = n0 >> 10;
    const int bh = (n0 >> 5) & 31;
    const int bw = n0 & 31;                  // bw..bw+3, same (b,bh) band

    // Lane covers rows (lane>>3)+4r, r=0..7; 8 lanes per 128B row segment.
    const int4* base = reinterpret_cast<const int4*>(targets)
                     + (size_t)b * (Hc * Wc / 4)
                     + (size_t)(bh * 32 + (lane >> 3)) * (Wc / 4)
                     + bw * 8 + (lane & 7);

    float    acc    = 0.0f;
    float    x_prev = 0.0f;
    unsigned m_prev = 0u;

    #pragma unroll
    for (int i = 0; i < TPW; i++) {
        const int4* p = base + i * 8;        // next tile: +32 ints
        // Issue tile i's 8 independent loads (front-batched).
        int4 v0 = __ldg(p + 0 * 1024);
        int4 v1 = __ldg(p + 1 * 1024);
        int4 v2 = __ldg(p + 2 * 1024);
        int4 v3 = __ldg(p + 3 * 1024);
        int4 v4 = __ldg(p + 4 * 1024);
        int4 v5 = __ldg(p + 5 * 1024);
        int4 v6 = __ldg(p + 6 * 1024);
        int4 v7 = __ldg(p + 7 * 1024);
        float x_cur = (lane < Cc) ? __ldg(&preds[(n0 + i) * Cc + lane]) : 0.0f;

        // Finish tile i-1 while tile i's loads are in flight.
        if (i > 0) {
            unsigned mm = __reduce_or_sync(0xffffffffu, m_prev);
            if (lane < Cc)
                acc += bce_logit(x_prev, (float)((mm >> lane) & 1u));
        }

        // Consume tile i (stalls here only until data lands).
        unsigned m = (1u << v0.x) | (1u << v0.y) | (1u << v0.z) | (1u << v0.w);
        m |= (1u << v1.x) | (1u << v1.y) | (1u << v1.z) | (1u << v1.w);
        m |= (1u << v2.x) | (1u << v2.y) | (1u << v2.z) | (1u << v2.w);
        m |= (1u << v3.x) | (1u << v3.y) | (1u << v3.z) | (1u << v3.w);
        m |= (1u << v4.x) | (1u << v4.y) | (1u << v4.z) | (1u << v4.w);
        m |= (1u << v5.x) | (1u << v5.y) | (1u << v5.z) | (1u << v5.w);
        m |= (1u << v6.x) | (1u << v6.y) | (1u << v6.z) | (1u << v6.w);
        m |= (1u << v7.x) | (1u << v7.y) | (1u << v7.z) | (1u << v7.w);
        m_prev = m;
        x_prev = x_cur;
    }
    // Epilogue: finish last tile.
    {
        unsigned mm = __reduce_or_sync(0xffffffffu, m_prev);
        if (lane < Cc)
            acc += bce_logit(x_prev, (float)((mm >> lane) & 1u));
    }

    // One shfl reduction per warp for all 4 tiles.
    #pragma unroll
    for (int o = 16; o > 0; o >>= 1)
        acc += __shfl_down_sync(0xffffffffu, acc, o);

    __shared__ float s_part[WPC];
    if (lane == 0) s_part[warp] = acc;
    __syncthreads();
    if (warp != 0) return;                  // only warp0 pays the atomic cost

    float cs = (lane < WPC) ? s_part[lane] : 0.0f;
    #pragma unroll
    for (int o = 4; o > 0; o >>= 1)
        cs += __shfl_down_sync(0xffffffffu, cs, o);

    int is_last = 0;
    if (lane == 0) {
        g_part[blockIdx.x] = cs;
        __threadfence();
        unsigned old = atomicInc(&g_count, NCTA - 1u);  // replay-safe wrap
        is_last = (old == NCTA - 1u);
    }
    is_last = __shfl_sync(0xffffffffu, is_last, 0);
    if (!is_last) return;

    // Last CTA's warp0: reduce 1024 partials (hot in L2).
    double s = 0.0;
    for (int i = lane; i < NCTA; i += 32)
        s += (double)__ldcg(&g_part[i]);
    #pragma unroll
    for (int o = 16; o > 0; o >>= 1)
        s += __shfl_down_sync(0xffffffffu, s, o);
    if (lane == 0)
        out[0] = (float)(s / ((double)NBLK * (double)Cc));
}

extern "C" void kernel_launch(void* const* d_in, const int* in_sizes, int n_in,
                              void* d_out, int out_size) {
    const float* preds   = (const float*)d_in[0];
    const int*   targets = (const int*)d_in[1];
    float*       out     = (float*)d_out;

    seg_fused_kernel<<<NCTA, 256>>>(preds, targets, out);
}

// round 5
// speedup vs baseline: 1.2807x; 1.1272x over previous
#include <cuda_runtime.h>
#include <cuda_bf16.h>
#include <cstdint>

// SegEncodeLoss round 5: bulk-async (UBLKCP) streaming.
// r2-r4 all plateaued at ~4.2 TB/s = ~16 B/cyc/SM: the per-lane LDG L1tex
// wavefront-replay ceiling (512B LDG.128 spanning 16 sectors @ ~2cyc/wf).
// Fix: stream targets via 1D cp.async.bulk into smem (TMA path, no per-lane
// cost), build masks with conflict-free LDS.128.
//
// Layout: band = 32 image rows = 32 tiles = contiguous 128KB.
// 256 CTAs x 4 bands; 2-stage 32KB smem ring; chunk = 8 rows (quarter band).

constexpr int Cc     = 19;
constexpr int NBLK   = 32768;          // tiles
constexpr int NCTA   = 256;
constexpr int BPC    = 4;              // bands per CTA
constexpr int CPB    = 4;              // chunks per band
constexpr int NCHUNK = BPC * CPB;      // 16
constexpr int CHUNK_B = 32768;         // 8 rows * 4KB

__device__ float    g_part[NCTA];
__device__ unsigned g_count = 0;       // self-resets via atomicInc wrap

__device__ __forceinline__ uint32_t smem_u32(const void* p) {
    uint32_t a;
    asm("{ .reg .u64 t; cvta.to.shared.u64 t, %1; cvt.u32.u64 %0, t; }"
        : "=r"(a) : "l"(p));
    return a;
}
__device__ __forceinline__ void mbar_init(uint32_t mbar, uint32_t cnt) {
    asm volatile("mbarrier.init.shared.b64 [%0], %1;" :: "r"(mbar), "r"(cnt) : "memory");
}
__device__ __forceinline__ void mbar_expect_tx(uint32_t mbar, uint32_t bytes) {
    asm volatile("mbarrier.arrive.expect_tx.shared.b64 _, [%0], %1;"
                 :: "r"(mbar), "r"(bytes) : "memory");
}
__device__ __forceinline__ void bulk_g2s(uint32_t dst, const void* src,
                                         uint32_t bytes, uint32_t mbar) {
    asm volatile(
        "cp.async.bulk.shared::cta.global.mbarrier::complete_tx::bytes "
        "[%0], [%1], %2, [%3];"
        :: "r"(dst), "l"(src), "r"(bytes), "r"(mbar) : "memory");
}
__device__ __forceinline__ void mbar_wait(uint32_t mbar, uint32_t parity) {
    asm volatile(
        "{\n\t"
        ".reg .pred P;\n\t"
        "WL_%=:\n\t"
        "mbarrier.try_wait.parity.acquire.cta.shared::cta.b64 P, [%0], %1, 0x989680;\n\t"
        "@P bra.uni WD_%=;\n\t"
        "bra.uni WL_%=;\n\t"
        "WD_%=:\n\t"
        "}"
        :: "r"(mbar), "r"(parity) : "memory");
}
__device__ __forceinline__ float bce_logit(float x, float t) {
    return fmaxf(x, 0.0f) - x * t + log1pf(__expf(-fabsf(x)));
}

__global__ void __launch_bounds__(256) seg_bulk_kernel(
    const float* __restrict__ preds,
    const int*   __restrict__ targets,
    float*       __restrict__ out)
{
    extern __shared__ char smem[];
    int4* buf = reinterpret_cast<int4*>(smem);              // 2 x 32KB
    uint64_t* mbar_mem = reinterpret_cast<uint64_t*>(smem + 2 * CHUNK_B);
    unsigned* s_mask   = reinterpret_cast<unsigned*>(smem + 2 * CHUNK_B + 64); // 32
    float*    s_part   = reinterpret_cast<float*>(smem + 2 * CHUNK_B + 64 + 128);

    const int tid  = threadIdx.x;
    const int warp = tid >> 5;
    const int lane = tid & 31;
    const uint32_t mb0 = smem_u32(&mbar_mem[0]);
    const uint32_t mb1 = smem_u32(&mbar_mem[1]);

    if (tid == 0) { mbar_init(mb0, 1); mbar_init(mb1, 1); }
    __syncthreads();

    const char* src_base = reinterpret_cast<const char*>(targets)
                         + (size_t)blockIdx.x * BPC * CPB * CHUNK_B;

    // Prologue: fill both ring stages.
    if (tid == 0) {
        mbar_expect_tx(mb0, CHUNK_B);
        bulk_g2s(smem_u32(&buf[0]), src_base + 0 * CHUNK_B, CHUNK_B, mb0);
        mbar_expect_tx(mb1, CHUNK_B);
        bulk_g2s(smem_u32(&buf[CHUNK_B / 16]), src_base + 1 * CHUNK_B, CHUNK_B, mb1);
    }

    float    acc = 0.0f;
    unsigned m   = 0u;
    float    xr0 = 0, xr1 = 0, xr2 = 0, xr3 = 0;

    for (int k = 0; k < NCHUNK; k++) {
        const int s = k & 1;
        if ((k & 3) == 0) {
            // Band start: prefetch this warp's 4 logit rows (independent of masks).
            const int band = blockIdx.x * BPC + (k >> 2);
            const int n0   = band * 32 + warp * 4;
            if (lane < Cc) {
                xr0 = __ldg(&preds[(n0 + 0) * Cc + lane]);
                xr1 = __ldg(&preds[(n0 + 1) * Cc + lane]);
                xr2 = __ldg(&preds[(n0 + 2) * Cc + lane]);
                xr3 = __ldg(&preds[(n0 + 3) * Cc + lane]);
            }
        }

        mbar_wait(s ? mb1 : mb0, (k >> 1) & 1);

        // Warp w owns the 512B column stripe [512w, 512w+512) = tiles 4w..4w+3.
        // 8 rows per chunk, LDS.128 contiguous per row: conflict-free.
        const int4* bb = buf + s * (CHUNK_B / 16) + warp * 32 + lane;
        #pragma unroll
        for (int r = 0; r < 8; r++) {
            int4 v = bb[r * 256];
            m |= (1u << v.x) | (1u << v.y) | (1u << v.z) | (1u << v.w);
        }
        __syncthreads();                         // all readers done with buf[s]

        if (k + 2 < NCHUNK && tid == 0) {
            mbar_expect_tx(s ? mb1 : mb0, CHUNK_B);
            bulk_g2s(smem_u32(&buf[s * (CHUNK_B / 16)]),
                     src_base + (size_t)(k + 2) * CHUNK_B, CHUNK_B, s ? mb1 : mb0);
        }

        if ((k & 3) == 3) {
            // Band done: OR over the 8-lane group -> full tile mask.
            m |= __shfl_xor_sync(0xffffffffu, m, 1);
            m |= __shfl_xor_sync(0xffffffffu, m, 2);
            m |= __shfl_xor_sync(0xffffffffu, m, 4);
            if ((lane & 7) == 0) s_mask[warp * 4 + (lane >> 3)] = m;
            __syncthreads();
            if (lane < Cc) {
                const unsigned m0 = s_mask[warp * 4 + 0];
                const unsigned m1 = s_mask[warp * 4 + 1];
                const unsigned m2 = s_mask[warp * 4 + 2];
                const unsigned m3 = s_mask[warp * 4 + 3];
                acc += bce_logit(xr0, (float)((m0 >> lane) & 1u));
                acc += bce_logit(xr1, (float)((m1 >> lane) & 1u));
                acc += bce_logit(xr2, (float)((m2 >> lane) & 1u));
                acc += bce_logit(xr3, (float)((m3 >> lane) & 1u));
            }
            m = 0u;
        }
    }

    // Warp sum -> CTA sum -> global partial -> last-CTA finish.
    #pragma unroll
    for (int o = 16; o > 0; o >>= 1)
        acc += __shfl_down_sync(0xffffffffu, acc, o);
    if (lane == 0) s_part[warp] = acc;
    __syncthreads();
    if (warp != 0) return;

    float cs = (lane < 8) ? s_part[lane] : 0.0f;
    #pragma unroll
    for (int o = 4; o > 0; o >>= 1)
        cs += __shfl_down_sync(0xffffffffu, cs, o);

    int is_last = 0;
    if (lane == 0) {
        g_part[blockIdx.x] = cs;
        __threadfence();
        unsigned old = atomicInc(&g_count, NCTA - 1u);   // wraps: replay-safe
        is_last = (old == NCTA - 1u);
    }
    is_last = __shfl_sync(0xffffffffu, is_last, 0);
    if (!is_last) return;

    double sd = 0.0;
    for (int i = lane; i < NCTA; i += 32)
        sd += (double)__ldcg(&g_part[i]);
    #pragma unroll
    for (int o = 16; o > 0; o >>= 1)
        sd += __shfl_down_sync(0xffffffffu, sd, o);
    if (lane == 0)
        out[0] = (float)(sd / ((double)NBLK * (double)Cc));
}

extern "C" void kernel_launch(void* const* d_in, const int* in_sizes, int n_in,
                              void* d_out, int out_size) {
    const float* preds   = (const float*)d_in[0];
    const int*   targets = (const int*)d_in[1];
    float*       out     = (float*)d_out;

    const int smem_bytes = 2 * CHUNK_B + 64 + 128 + 64;   // ring + mbars + masks + partials
    cudaFuncSetAttribute(seg_bulk_kernel,
                         cudaFuncAttributeMaxDynamicSharedMemorySize, smem_bytes);
    seg_bulk_kernel<<<NCTA, 256, smem_bytes>>>(preds, targets, out);
}